// round 8
// baseline (speedup 1.0000x reference)
#include <cuda_runtime.h>
#include <cuda_bf16.h>

// ---------------- problem constants ----------------
#define BB    64
#define LL    256
#define EE    512
#define DD    512
#define MROWS (BB * LL)        // 16384
#define CATW  2048             // [x(512) | ctx(512) | attended(1024)]

// ---------------- scratch (static device globals; no allocations) ----------
__device__ float g_cmp_p[MROWS * CATW];      // prem  [x|ctx|att_hypo]
__device__ float g_cmp_h[MROWS * CATW];      // hypo  [x|ctx|att_prem]
__device__ float g_hid  [MROWS * DD];
__device__ float g_pq   [MROWS * DD];
__device__ float g_hk   [MROWS * DD];
__device__ float g_s1   [BB * LL * LL];      // scores / z / p2h
__device__ float g_s2   [BB * LL * LL];      // h2p
__device__ float g_agg  [BB * 2 * DD];       // [prem_cmp | hypo_cmp]
__device__ int   g_mask_p[MROWS];
__device__ int   g_mask_h[MROWS];

__device__ __forceinline__ float relu_(float x) { return x > 0.f ? x : 0.f; }

// =====================================================================
// SGEMM: C = act(op(A) @ op(B) + bias), 128x128x16 tiles, double buffered
//   A: [M,K] row-major (lda).  B: NN -> [K,N] (ldb); NT -> [N,K] (ldb).
//   grid = (N/128, M/128, batch). Dims must be multiples of 128 / 16.
// =====================================================================
template<bool NT, bool BIAS, bool RELU>
__global__ void __launch_bounds__(256)
sgemm_k(const float* __restrict__ A, const float* __restrict__ B,
        const float* __restrict__ bias, float* __restrict__ C,
        int K, int lda, int ldb, int ldc,
        long long sA, long long sB, long long sC)
{
    __shared__ float As[2][16][132];
    __shared__ float Bs[2][16][132];

    const int tid = threadIdx.x;
    const int bm = blockIdx.y << 7;
    const int bn = blockIdx.x << 7;
    A += (long long)blockIdx.z * sA;
    B += (long long)blockIdx.z * sB;
    C += (long long)blockIdx.z * sC;

    // A tile loader mapping (also used for NT B): 64 rows x (4-float) cols
    const int lm = tid >> 2;            // 0..63
    const int lk = (tid & 3) << 2;      // 0,4,8,12

    const float* Ap0 = A + (long long)(bm + lm) * lda + lk;
    const float* Ap1 = Ap0 + (long long)64 * lda;

    const float* Bp0;
    const float* Bp1;
    int bkr = 0, bnc = 0;
    if (NT) {
        Bp0 = B + (long long)(bn + lm) * ldb + lk;
        Bp1 = Bp0 + (long long)64 * ldb;
    } else {
        bkr = tid >> 5;                 // 0..7
        bnc = (tid & 31) << 2;          // 0..124
        Bp0 = B + (long long)bkr * ldb + bn + bnc;
        Bp1 = Bp0 + (long long)8 * ldb;
    }

    const int cr = (tid >> 4) << 3;     // 0..120
    const int cc = (tid & 15) << 3;     // 0..120

    float acc[8][8];
#pragma unroll
    for (int i = 0; i < 8; i++)
#pragma unroll
        for (int j = 0; j < 8; j++) acc[i][j] = 0.f;

    // ---- stage 0 load ----
    {
        float4 a0 = *(const float4*)Ap0;
        float4 a1 = *(const float4*)Ap1;
        As[0][lk + 0][lm] = a0.x; As[0][lk + 1][lm] = a0.y;
        As[0][lk + 2][lm] = a0.z; As[0][lk + 3][lm] = a0.w;
        As[0][lk + 0][lm + 64] = a1.x; As[0][lk + 1][lm + 64] = a1.y;
        As[0][lk + 2][lm + 64] = a1.z; As[0][lk + 3][lm + 64] = a1.w;
        if (NT) {
            float4 b0 = *(const float4*)Bp0;
            float4 b1 = *(const float4*)Bp1;
            Bs[0][lk + 0][lm] = b0.x; Bs[0][lk + 1][lm] = b0.y;
            Bs[0][lk + 2][lm] = b0.z; Bs[0][lk + 3][lm] = b0.w;
            Bs[0][lk + 0][lm + 64] = b1.x; Bs[0][lk + 1][lm + 64] = b1.y;
            Bs[0][lk + 2][lm + 64] = b1.z; Bs[0][lk + 3][lm + 64] = b1.w;
        } else {
            *(float4*)&Bs[0][bkr][bnc]     = *(const float4*)Bp0;
            *(float4*)&Bs[0][bkr + 8][bnc] = *(const float4*)Bp1;
        }
    }
    __syncthreads();

    const int KT = K >> 4;
    int buf = 0;
    for (int kt = 0; kt < KT; ++kt) {
        float4 na0, na1, nb0, nb1;
        const bool has_next = (kt + 1 < KT);
        if (has_next) {
            na0 = *(const float4*)(Ap0 + (kt + 1) * 16);
            na1 = *(const float4*)(Ap1 + (kt + 1) * 16);
            if (NT) {
                nb0 = *(const float4*)(Bp0 + (kt + 1) * 16);
                nb1 = *(const float4*)(Bp1 + (kt + 1) * 16);
            } else {
                nb0 = *(const float4*)(Bp0 + (long long)(kt + 1) * 16 * ldb);
                nb1 = *(const float4*)(Bp1 + (long long)(kt + 1) * 16 * ldb);
            }
        }

#pragma unroll
        for (int kk = 0; kk < 16; ++kk) {
            float av[8], bv[8];
            *(float4*)&av[0] = *(const float4*)&As[buf][kk][cr];
            *(float4*)&av[4] = *(const float4*)&As[buf][kk][cr + 4];
            *(float4*)&bv[0] = *(const float4*)&Bs[buf][kk][cc];
            *(float4*)&bv[4] = *(const float4*)&Bs[buf][kk][cc + 4];
#pragma unroll
            for (int i = 0; i < 8; i++)
#pragma unroll
                for (int j = 0; j < 8; j++)
                    acc[i][j] = fmaf(av[i], bv[j], acc[i][j]);
        }

        if (has_next) {
            const int nb = buf ^ 1;
            As[nb][lk + 0][lm] = na0.x; As[nb][lk + 1][lm] = na0.y;
            As[nb][lk + 2][lm] = na0.z; As[nb][lk + 3][lm] = na0.w;
            As[nb][lk + 0][lm + 64] = na1.x; As[nb][lk + 1][lm + 64] = na1.y;
            As[nb][lk + 2][lm + 64] = na1.z; As[nb][lk + 3][lm + 64] = na1.w;
            if (NT) {
                Bs[nb][lk + 0][lm] = nb0.x; Bs[nb][lk + 1][lm] = nb0.y;
                Bs[nb][lk + 2][lm] = nb0.z; Bs[nb][lk + 3][lm] = nb0.w;
                Bs[nb][lk + 0][lm + 64] = nb1.x; Bs[nb][lk + 1][lm + 64] = nb1.y;
                Bs[nb][lk + 2][lm + 64] = nb1.z; Bs[nb][lk + 3][lm + 64] = nb1.w;
            } else {
                *(float4*)&Bs[nb][bkr][bnc]     = nb0;
                *(float4*)&Bs[nb][bkr + 8][bnc] = nb1;
            }
            __syncthreads();
            buf = nb;
        }
    }

    // ---- epilogue ----
    float bb[8];
    if (BIAS) {
#pragma unroll
        for (int j = 0; j < 8; j++) bb[j] = bias[bn + cc + j];
    }
#pragma unroll
    for (int i = 0; i < 8; i++) {
        float v[8];
#pragma unroll
        for (int j = 0; j < 8; j++) {
            float x = acc[i][j];
            if (BIAS) x += bb[j];
            if (RELU) x = relu_(x);
            v[j] = x;
        }
        float* cp = C + (long long)(bm + cr + i) * ldc + bn + cc;
        *(float4*)cp       = make_float4(v[0], v[1], v[2], v[3]);
        *(float4*)(cp + 4) = make_float4(v[4], v[5], v[6], v[7]);
    }
}

// =====================================================================
// embedding gather into the wide concat buffer (cols 0..511), + mask
// =====================================================================
__global__ void embed_k(const int* __restrict__ tok, const float* __restrict__ W,
                        float* __restrict__ out, int* __restrict__ mask)
{
    const int r = blockIdx.x;
    const int t = tok[r];
    if (threadIdx.x == 0) mask[r] = (t != 0);
    const float4* src = (const float4*)(W + (long long)t * EE);
    float4* dst = (float4*)(out + (long long)r * CATW);
    dst[threadIdx.x] = src[threadIdx.x];   // 128 threads x 16B = 512 floats
}

// ---------------- block reductions (blockDim = 256) ----------------
__device__ __forceinline__ float blockMax256(float v, float* red)
{
#pragma unroll
    for (int o = 16; o; o >>= 1) v = fmaxf(v, __shfl_xor_sync(0xffffffffu, v, o));
    if ((threadIdx.x & 31) == 0) red[threadIdx.x >> 5] = v;
    __syncthreads();
    float m = red[0];
#pragma unroll
    for (int i = 1; i < 8; i++) m = fmaxf(m, red[i]);
    return m;
}
__device__ __forceinline__ float blockSum256(float v, float* red)
{
#pragma unroll
    for (int o = 16; o; o >>= 1) v += __shfl_xor_sync(0xffffffffu, v, o);
    if ((threadIdx.x & 31) == 0) red[threadIdx.x >> 5] = v;
    __syncthreads();
    float s = red[0];
#pragma unroll
    for (int i = 1; i < 8; i++) s += red[i];
    return s;
}

// self-attention softmax (in place): rel bias, diag=-inf, padded key=-1e9
__global__ void softmax_self_k(float* __restrict__ S, const int* __restrict__ mask,
                               const float* __restrict__ distW)
{
    const int q = blockIdx.x, b = blockIdx.y, k = threadIdx.x;
    float* row = S + ((long long)(b * LL + q)) * LL;
    __shared__ float red[8];
    __shared__ float dw[23];
    if (k < 23) dw[k] = distW[k];
    const int valid = mask[b * LL + k];
    const float sc = row[k];
    __syncthreads();

    float v;
    if (!valid)      v = -1e9f;
    else if (k == q) v = __int_as_float(0xff800000);   // -inf
    else {
        int d = k - q; d = d < -11 ? -11 : (d > 11 ? 11 : d);
        v = sc + dw[d + 11];
    }
    const float m = blockMax256(v, red);
    __syncthreads();
    const float e = expf(v - m);
    const float s = blockSum256(e, red);
    row[k] = e / s;
}

// row softmax with key mask (in place)
__global__ void softmax_rows_k(float* __restrict__ Z, const int* __restrict__ mask)
{
    const int q = blockIdx.x, b = blockIdx.y, k = threadIdx.x;
    float* row = Z + ((long long)(b * LL + q)) * LL;
    __shared__ float red[8];
    const float v = mask[b * LL + k] ? row[k] : -1e9f;
    const float m = blockMax256(v, red);
    __syncthreads();
    const float e = expf(v - m);
    const float s = blockSum256(e, red);
    row[k] = e / s;
}

// column softmax: Out[b,h,p] = softmax_p( Z[b,p,h] masked by maskP[p] )
__global__ void softmax_cols_k(const float* __restrict__ Z, const int* __restrict__ maskP,
                               float* __restrict__ Out)
{
    const int h = blockIdx.x, b = blockIdx.y, p = threadIdx.x;
    __shared__ float red[8];
    const float v = maskP[b * LL + p]
                  ? Z[((long long)(b * LL + p)) * LL + h] : -1e9f;
    const float m = blockMax256(v, red);
    __syncthreads();
    const float e = expf(v - m);
    const float s = blockSum256(e, red);
    Out[((long long)(b * LL + h)) * LL + p] = e / s;
}

// masked sum over sequence: out[b*1024 + off + d] = sum_l mask * X[b,l,d]
__global__ void masked_sum_k(const float* __restrict__ X, const int* __restrict__ mask,
                             float* __restrict__ out, int off)
{
    const int b = blockIdx.y;
    const int d = blockIdx.x * 128 + threadIdx.x;
    const float* xb = X + (long long)b * LL * DD;
    const int* mb = mask + b * LL;
    float acc = 0.f;
    for (int l = 0; l < LL; l++)
        if (mb[l]) acc += xb[l * DD + d];
    out[b * (2 * DD) + off + d] = acc;
}

// aggregate MLP + output head (tiny): 64 blocks x 512 threads
__global__ void head_k(const float* __restrict__ aggin,
                       const float* __restrict__ Wg1, const float* __restrict__ bg1,
                       const float* __restrict__ Wg2, const float* __restrict__ bg2,
                       const float* __restrict__ Wo, float* __restrict__ out)
{
    __shared__ float sin[2 * DD];
    __shared__ float h1[DD];
    __shared__ float h2[DD];
    const int b = blockIdx.x, t = threadIdx.x;
    sin[t]       = aggin[b * 2 * DD + t];
    sin[t + DD]  = aggin[b * 2 * DD + DD + t];
    __syncthreads();
    float a = bg1[t];
    for (int k = 0; k < 2 * DD; k++) a = fmaf(sin[k], Wg1[k * DD + t], a);
    h1[t] = relu_(a);
    __syncthreads();
    a = bg2[t];
    for (int k = 0; k < DD; k++) a = fmaf(h1[k], Wg2[k * DD + t], a);
    h2[t] = relu_(a);
    __syncthreads();
    if (t < 3) {
        float s = 0.f;
        for (int k = 0; k < DD; k++) s = fmaf(h2[k], Wo[k * 3 + t], s);
        out[b * 3 + t] = s;
    }
}

// ---------------- host-side GEMM dispatch ----------------
enum GType { G_MLP, G_NN, G_NT };
static void gemm(GType t, const float* A, const float* B, const float* bias, float* C,
                 int M, int N, int K, int lda, int ldb, int ldc,
                 long long sA, long long sB, long long sC, int batch)
{
    dim3 grid(N >> 7, M >> 7, batch), blk(256);
    switch (t) {
    case G_MLP: sgemm_k<false, true,  true ><<<grid, blk>>>(A, B, bias, C, K, lda, ldb, ldc, sA, sB, sC); break;
    case G_NN:  sgemm_k<false, false, false><<<grid, blk>>>(A, B, bias, C, K, lda, ldb, ldc, sA, sB, sC); break;
    case G_NT:  sgemm_k<true,  false, false><<<grid, blk>>>(A, B, bias, C, K, lda, ldb, ldc, sA, sB, sC); break;
    }
}

extern "C" void kernel_launch(void* const* d_in, const int* in_sizes, int n_in,
                              void* d_out, int out_size)
{
    (void)in_sizes; (void)n_in; (void)out_size;
    const int*   prem  = (const int*)  d_in[0];
    const int*   hypo  = (const int*)  d_in[1];
    const float* embW  = (const float*)d_in[2];
    const float* distW = (const float*)d_in[3];
    const float* Ws1 = (const float*)d_in[4];  const float* bs1 = (const float*)d_in[5];
    const float* Ws2 = (const float*)d_in[6];  const float* bs2 = (const float*)d_in[7];
    const float* Wa1 = (const float*)d_in[8];  const float* ba1 = (const float*)d_in[9];
    const float* Wa2 = (const float*)d_in[10]; const float* ba2 = (const float*)d_in[11];
    const float* Wc1 = (const float*)d_in[12]; const float* bc1 = (const float*)d_in[13];
    const float* Wc2 = (const float*)d_in[14]; const float* bc2 = (const float*)d_in[15];
    const float* Wg1 = (const float*)d_in[16]; const float* bg1 = (const float*)d_in[17];
    const float* Wg2 = (const float*)d_in[18]; const float* bg2 = (const float*)d_in[19];
    const float* Wo  = (const float*)d_in[20];
    float* out = (float*)d_out;

    float *cmp_p, *cmp_h, *hid, *pq, *hk, *s1, *s2, *agg;
    int *mp, *mh;
    cudaGetSymbolAddress((void**)&cmp_p, g_cmp_p);
    cudaGetSymbolAddress((void**)&cmp_h, g_cmp_h);
    cudaGetSymbolAddress((void**)&hid,   g_hid);
    cudaGetSymbolAddress((void**)&pq,    g_pq);
    cudaGetSymbolAddress((void**)&hk,    g_hk);
    cudaGetSymbolAddress((void**)&s1,    g_s1);
    cudaGetSymbolAddress((void**)&s2,    g_s2);
    cudaGetSymbolAddress((void**)&agg,   g_agg);
    cudaGetSymbolAddress((void**)&mp,    g_mask_p);
    cudaGetSymbolAddress((void**)&mh,    g_mask_h);

    const long long SQ  = (long long)LL * DD;     // 256*512  per-batch Q stride
    const long long SS  = (long long)LL * LL;     // 256*256  per-batch score stride
    const long long SC  = (long long)LL * CATW;   // 256*2048 per-batch concat stride

    // embeddings -> concat[:, 0:512], masks
    embed_k<<<MROWS, 128>>>(prem, embW, cmp_p, mp);
    embed_k<<<MROWS, 128>>>(hypo, embW, cmp_h, mh);

    // ---- self branch: prem ----
    gemm(G_MLP, cmp_p, Ws1, bs1, hid, MROWS, DD, EE,   CATW, DD, DD, 0, 0, 0, 1);
    gemm(G_MLP, hid,   Ws2, bs2, pq,  MROWS, DD, DD,   DD,   DD, DD, 0, 0, 0, 1);
    gemm(G_NT,  pq, pq, nullptr, s1,  LL, LL, DD, DD, DD, LL, SQ, SQ, SS, BB);
    softmax_self_k<<<dim3(LL, BB), 256>>>(s1, mp, distW);
    gemm(G_NN,  s1, cmp_p, nullptr, cmp_p + EE, LL, EE, LL, LL, CATW, CATW, SS, SC, SC, BB);

    // ---- self branch: hypo ----
    gemm(G_MLP, cmp_h, Ws1, bs1, hid, MROWS, DD, EE,   CATW, DD, DD, 0, 0, 0, 1);
    gemm(G_MLP, hid,   Ws2, bs2, pq,  MROWS, DD, DD,   DD,   DD, DD, 0, 0, 0, 1);
    gemm(G_NT,  pq, pq, nullptr, s1,  LL, LL, DD, DD, DD, LL, SQ, SQ, SS, BB);
    softmax_self_k<<<dim3(LL, BB), 256>>>(s1, mh, distW);
    gemm(G_NN,  s1, cmp_h, nullptr, cmp_h + EE, LL, EE, LL, LL, CATW, CATW, SS, SC, SC, BB);

    // ---- inter attention ----
    gemm(G_MLP, cmp_p, Wa1, ba1, hid, MROWS, DD, 2 * EE, CATW, DD, DD, 0, 0, 0, 1);
    gemm(G_MLP, hid,   Wa2, ba2, pq,  MROWS, DD, DD,     DD,   DD, DD, 0, 0, 0, 1);
    gemm(G_MLP, cmp_h, Wa1, ba1, hid, MROWS, DD, 2 * EE, CATW, DD, DD, 0, 0, 0, 1);
    gemm(G_MLP, hid,   Wa2, ba2, hk,  MROWS, DD, DD,     DD,   DD, DD, 0, 0, 0, 1);
    gemm(G_NT,  pq, hk, nullptr, s1,  LL, LL, DD, DD, DD, LL, SQ, SQ, SS, BB);
    softmax_cols_k<<<dim3(LL, BB), 256>>>(s1, mp, s2);   // hypo2prem (reads cols of z)
    softmax_rows_k<<<dim3(LL, BB), 256>>>(s1, mh);       // prem2hypo (in place)
    // attended_hypo -> cmp_p[:, 1024:2048]
    gemm(G_NN, s1, cmp_h, nullptr, cmp_p + 2 * EE, LL, 2 * EE, LL, LL, CATW, CATW, SS, SC, SC, BB);
    // attended_prem -> cmp_h[:, 1024:2048]
    gemm(G_NN, s2, cmp_p, nullptr, cmp_h + 2 * EE, LL, 2 * EE, LL, LL, CATW, CATW, SS, SC, SC, BB);

    // ---- compare + masked sum ----
    gemm(G_MLP, cmp_p, Wc1, bc1, hid, MROWS, DD, 4 * EE, CATW, DD, DD, 0, 0, 0, 1);
    gemm(G_MLP, hid,   Wc2, bc2, pq,  MROWS, DD, DD,     DD,   DD, DD, 0, 0, 0, 1);
    masked_sum_k<<<dim3(DD / 128, BB), 128>>>(pq, mp, agg, 0);
    gemm(G_MLP, cmp_h, Wc1, bc1, hid, MROWS, DD, 4 * EE, CATW, DD, DD, 0, 0, 0, 1);
    gemm(G_MLP, hid,   Wc2, bc2, pq,  MROWS, DD, DD,     DD,   DD, DD, 0, 0, 0, 1);
    masked_sum_k<<<dim3(DD / 128, BB), 128>>>(pq, mh, agg, DD);

    // ---- aggregate MLP + output ----
    head_k<<<BB, DD>>>(agg, Wg1, bg1, Wg2, bg2, Wo, out);
}

// round 9
// speedup vs baseline: 1.0299x; 1.0299x over previous
#include <cuda_runtime.h>
#include <cuda_bf16.h>

// ---------------- problem constants ----------------
#define BB    64
#define LL    256
#define EE    512
#define DD    512
#define MROWS (BB * LL)        // 16384
#define CATW  2048             // [x(512) | ctx(512) | attended(1024)]

// ---------------- scratch (static device globals; no allocations) ----------
__device__ float g_cmp_p[MROWS * CATW];      // prem  [x|ctx|att_hypo]
__device__ float g_cmp_h[MROWS * CATW];      // hypo  [x|ctx|att_prem]
__device__ float g_hid  [MROWS * DD];
__device__ float g_pq   [MROWS * DD];
__device__ float g_hk   [MROWS * DD];
__device__ float g_s1   [BB * LL * LL];      // scores / z / p2h
__device__ float g_s2   [BB * LL * LL];      // h2p
__device__ float g_agg  [BB * 2 * DD];       // [prem_cmp | hypo_cmp]
__device__ int   g_mask_p[MROWS];
__device__ int   g_mask_h[MROWS];

__device__ __forceinline__ float relu_(float x) { return x > 0.f ? x : 0.f; }

// =====================================================================
// SGEMM: C = act(op(A) @ op(B) + bias), 128x128x16 tiles, double buffered
//   A: [M,K] row-major (lda).  B: NN -> [K,N] (ldb); NT -> [N,K] (ldb).
//   grid = (N/128, M/128, batch). Dims must be multiples of 128 / 16.
//   __launch_bounds__(256, 2): 2 CTAs/SM (4 warps/SMSP) to cover LDS/sync
//   stalls — FMA pipe needs 2 back-to-back-issuing warps per SMSP.
// =====================================================================
template<bool NT, bool BIAS, bool RELU>
__global__ void __launch_bounds__(256, 2)
sgemm_k(const float* __restrict__ A, const float* __restrict__ B,
        const float* __restrict__ bias, float* __restrict__ C,
        int K, int lda, int ldb, int ldc,
        long long sA, long long sB, long long sC)
{
    __shared__ float As[2][16][132];
    __shared__ float Bs[2][16][132];

    const int tid = threadIdx.x;
    const int bm = blockIdx.y << 7;
    const int bn = blockIdx.x << 7;
    A += (long long)blockIdx.z * sA;
    B += (long long)blockIdx.z * sB;
    C += (long long)blockIdx.z * sC;

    // A tile loader mapping (also used for NT B): 64 rows x (4-float) cols
    const int lm = tid >> 2;            // 0..63
    const int lk = (tid & 3) << 2;      // 0,4,8,12

    const float* Ap0 = A + (long long)(bm + lm) * lda + lk;
    const float* Ap1 = Ap0 + (long long)64 * lda;

    const float* Bp0;
    const float* Bp1;
    int bkr = 0, bnc = 0;
    long long bstep = 16;               // pointer step per k-tile for B
    if (NT) {
        Bp0 = B + (long long)(bn + lm) * ldb + lk;
        Bp1 = Bp0 + (long long)64 * ldb;
    } else {
        bkr = tid >> 5;                 // 0..7
        bnc = (tid & 31) << 2;          // 0..124
        Bp0 = B + (long long)bkr * ldb + bn + bnc;
        Bp1 = Bp0 + (long long)8 * ldb;
        bstep = (long long)16 * ldb;
    }

    const int cr = (tid >> 4) << 3;     // 0..120
    const int cc = (tid & 15) << 3;     // 0..120

    float acc[8][8];
#pragma unroll
    for (int i = 0; i < 8; i++)
#pragma unroll
        for (int j = 0; j < 8; j++) acc[i][j] = 0.f;

    // ---- stage 0 load ----
    {
        float4 a0 = *(const float4*)Ap0;
        float4 a1 = *(const float4*)Ap1;
        As[0][lk + 0][lm] = a0.x; As[0][lk + 1][lm] = a0.y;
        As[0][lk + 2][lm] = a0.z; As[0][lk + 3][lm] = a0.w;
        As[0][lk + 0][lm + 64] = a1.x; As[0][lk + 1][lm + 64] = a1.y;
        As[0][lk + 2][lm + 64] = a1.z; As[0][lk + 3][lm + 64] = a1.w;
        if (NT) {
            float4 b0 = *(const float4*)Bp0;
            float4 b1 = *(const float4*)Bp1;
            Bs[0][lk + 0][lm] = b0.x; Bs[0][lk + 1][lm] = b0.y;
            Bs[0][lk + 2][lm] = b0.z; Bs[0][lk + 3][lm] = b0.w;
            Bs[0][lk + 0][lm + 64] = b1.x; Bs[0][lk + 1][lm + 64] = b1.y;
            Bs[0][lk + 2][lm + 64] = b1.z; Bs[0][lk + 3][lm + 64] = b1.w;
        } else {
            *(float4*)&Bs[0][bkr][bnc]     = *(const float4*)Bp0;
            *(float4*)&Bs[0][bkr + 8][bnc] = *(const float4*)Bp1;
        }
    }
    __syncthreads();

    const int KT = K >> 4;
    int buf = 0;
    for (int kt = 0; kt < KT; ++kt) {
        // advance source pointers (incremental — keeps address math cheap)
        Ap0 += 16; Ap1 += 16;
        Bp0 += bstep; Bp1 += bstep;

        float4 na0, na1, nb0, nb1;
        const bool has_next = (kt + 1 < KT);
        if (has_next) {
            na0 = *(const float4*)Ap0;
            na1 = *(const float4*)Ap1;
            nb0 = *(const float4*)Bp0;
            nb1 = *(const float4*)Bp1;
        }

#pragma unroll
        for (int kk = 0; kk < 16; ++kk) {
            float av[8], bv[8];
            *(float4*)&av[0] = *(const float4*)&As[buf][kk][cr];
            *(float4*)&av[4] = *(const float4*)&As[buf][kk][cr + 4];
            *(float4*)&bv[0] = *(const float4*)&Bs[buf][kk][cc];
            *(float4*)&bv[4] = *(const float4*)&Bs[buf][kk][cc + 4];
#pragma unroll
            for (int i = 0; i < 8; i++)
#pragma unroll
                for (int j = 0; j < 8; j++)
                    acc[i][j] = fmaf(av[i], bv[j], acc[i][j]);
        }

        if (has_next) {
            const int nb = buf ^ 1;
            As[nb][lk + 0][lm] = na0.x; As[nb][lk + 1][lm] = na0.y;
            As[nb][lk + 2][lm] = na0.z; As[nb][lk + 3][lm] = na0.w;
            As[nb][lk + 0][lm + 64] = na1.x; As[nb][lk + 1][lm + 64] = na1.y;
            As[nb][lk + 2][lm + 64] = na1.z; As[nb][lk + 3][lm + 64] = na1.w;
            if (NT) {
                Bs[nb][lk + 0][lm] = nb0.x; Bs[nb][lk + 1][lm] = nb0.y;
                Bs[nb][lk + 2][lm] = nb0.z; Bs[nb][lk + 3][lm] = nb0.w;
                Bs[nb][lk + 0][lm + 64] = nb1.x; Bs[nb][lk + 1][lm + 64] = nb1.y;
                Bs[nb][lk + 2][lm + 64] = nb1.z; Bs[nb][lk + 3][lm + 64] = nb1.w;
            } else {
                *(float4*)&Bs[nb][bkr][bnc]     = nb0;
                *(float4*)&Bs[nb][bkr + 8][bnc] = nb1;
            }
            __syncthreads();
            buf = nb;
        }
    }

    // ---- epilogue ----
    float bb[8];
    if (BIAS) {
#pragma unroll
        for (int j = 0; j < 8; j++) bb[j] = bias[bn + cc + j];
    }
#pragma unroll
    for (int i = 0; i < 8; i++) {
        float v[8];
#pragma unroll
        for (int j = 0; j < 8; j++) {
            float x = acc[i][j];
            if (BIAS) x += bb[j];
            if (RELU) x = relu_(x);
            v[j] = x;
        }
        float* cp = C + (long long)(bm + cr + i) * ldc + bn + cc;
        *(float4*)cp       = make_float4(v[0], v[1], v[2], v[3]);
        *(float4*)(cp + 4) = make_float4(v[4], v[5], v[6], v[7]);
    }
}

// =====================================================================
// embedding gather into the wide concat buffer (cols 0..511), + mask
// =====================================================================
__global__ void embed_k(const int* __restrict__ tok, const float* __restrict__ W,
                        float* __restrict__ out, int* __restrict__ mask)
{
    const int r = blockIdx.x;
    const int t = tok[r];
    if (threadIdx.x == 0) mask[r] = (t != 0);
    const float4* src = (const float4*)(W + (long long)t * EE);
    float4* dst = (float4*)(out + (long long)r * CATW);
    dst[threadIdx.x] = src[threadIdx.x];   // 128 threads x 16B = 512 floats
}

// ---------------- block reductions (blockDim = 256) ----------------
__device__ __forceinline__ float blockMax256(float v, float* red)
{
#pragma unroll
    for (int o = 16; o; o >>= 1) v = fmaxf(v, __shfl_xor_sync(0xffffffffu, v, o));
    if ((threadIdx.x & 31) == 0) red[threadIdx.x >> 5] = v;
    __syncthreads();
    float m = red[0];
#pragma unroll
    for (int i = 1; i < 8; i++) m = fmaxf(m, red[i]);
    return m;
}
__device__ __forceinline__ float blockSum256(float v, float* red)
{
#pragma unroll
    for (int o = 16; o; o >>= 1) v += __shfl_xor_sync(0xffffffffu, v, o);
    if ((threadIdx.x & 31) == 0) red[threadIdx.x >> 5] = v;
    __syncthreads();
    float s = red[0];
#pragma unroll
    for (int i = 1; i < 8; i++) s += red[i];
    return s;
}

// self-attention softmax (in place): rel bias, diag=-inf, padded key=-1e9
__global__ void softmax_self_k(float* __restrict__ S, const int* __restrict__ mask,
                               const float* __restrict__ distW)
{
    const int q = blockIdx.x, b = blockIdx.y, k = threadIdx.x;
    float* row = S + ((long long)(b * LL + q)) * LL;
    __shared__ float red[8];
    __shared__ float dw[23];
    if (k < 23) dw[k] = distW[k];
    const int valid = mask[b * LL + k];
    const float sc = row[k];
    __syncthreads();

    float v;
    if (!valid)      v = -1e9f;
    else if (k == q) v = __int_as_float(0xff800000);   // -inf
    else {
        int d = k - q; d = d < -11 ? -11 : (d > 11 ? 11 : d);
        v = sc + dw[d + 11];
    }
    const float m = blockMax256(v, red);
    __syncthreads();
    const float e = expf(v - m);
    const float s = blockSum256(e, red);
    row[k] = e / s;
}

// row softmax with key mask (in place)
__global__ void softmax_rows_k(float* __restrict__ Z, const int* __restrict__ mask)
{
    const int q = blockIdx.x, b = blockIdx.y, k = threadIdx.x;
    float* row = Z + ((long long)(b * LL + q)) * LL;
    __shared__ float red[8];
    const float v = mask[b * LL + k] ? row[k] : -1e9f;
    const float m = blockMax256(v, red);
    __syncthreads();
    const float e = expf(v - m);
    const float s = blockSum256(e, red);
    row[k] = e / s;
}

// column softmax: Out[b,h,p] = softmax_p( Z[b,p,h] masked by maskP[p] )
__global__ void softmax_cols_k(const float* __restrict__ Z, const int* __restrict__ maskP,
                               float* __restrict__ Out)
{
    const int h = blockIdx.x, b = blockIdx.y, p = threadIdx.x;
    __shared__ float red[8];
    const float v = maskP[b * LL + p]
                  ? Z[((long long)(b * LL + p)) * LL + h] : -1e9f;
    const float m = blockMax256(v, red);
    __syncthreads();
    const float e = expf(v - m);
    const float s = blockSum256(e, red);
    Out[((long long)(b * LL + h)) * LL + p] = e / s;
}

// masked sum over sequence: out[b*1024 + off + d] = sum_l mask * X[b,l,d]
__global__ void masked_sum_k(const float* __restrict__ X, const int* __restrict__ mask,
                             float* __restrict__ out, int off)
{
    const int b = blockIdx.y;
    const int d = blockIdx.x * 128 + threadIdx.x;
    const float* xb = X + (long long)b * LL * DD;
    const int* mb = mask + b * LL;
    float acc = 0.f;
    for (int l = 0; l < LL; l++)
        if (mb[l]) acc += xb[l * DD + d];
    out[b * (2 * DD) + off + d] = acc;
}

// aggregate MLP + output head (tiny): 64 blocks x 512 threads
__global__ void head_k(const float* __restrict__ aggin,
                       const float* __restrict__ Wg1, const float* __restrict__ bg1,
                       const float* __restrict__ Wg2, const float* __restrict__ bg2,
                       const float* __restrict__ Wo, float* __restrict__ out)
{
    __shared__ float sin[2 * DD];
    __shared__ float h1[DD];
    __shared__ float h2[DD];
    const int b = blockIdx.x, t = threadIdx.x;
    sin[t]       = aggin[b * 2 * DD + t];
    sin[t + DD]  = aggin[b * 2 * DD + DD + t];
    __syncthreads();
    float a = bg1[t];
    for (int k = 0; k < 2 * DD; k++) a = fmaf(sin[k], Wg1[k * DD + t], a);
    h1[t] = relu_(a);
    __syncthreads();
    a = bg2[t];
    for (int k = 0; k < DD; k++) a = fmaf(h1[k], Wg2[k * DD + t], a);
    h2[t] = relu_(a);
    __syncthreads();
    if (t < 3) {
        float s = 0.f;
        for (int k = 0; k < DD; k++) s = fmaf(h2[k], Wo[k * 3 + t], s);
        out[b * 3 + t] = s;
    }
}

// ---------------- host-side GEMM dispatch ----------------
enum GType { G_MLP, G_NN, G_NT };
static void gemm(GType t, const float* A, const float* B, const float* bias, float* C,
                 int M, int N, int K, int lda, int ldb, int ldc,
                 long long sA, long long sB, long long sC, int batch)
{
    dim3 grid(N >> 7, M >> 7, batch), blk(256);
    switch (t) {
    case G_MLP: sgemm_k<false, true,  true ><<<grid, blk>>>(A, B, bias, C, K, lda, ldb, ldc, sA, sB, sC); break;
    case G_NN:  sgemm_k<false, false, false><<<grid, blk>>>(A, B, bias, C, K, lda, ldb, ldc, sA, sB, sC); break;
    case G_NT:  sgemm_k<true,  false, false><<<grid, blk>>>(A, B, bias, C, K, lda, ldb, ldc, sA, sB, sC); break;
    }
}

extern "C" void kernel_launch(void* const* d_in, const int* in_sizes, int n_in,
                              void* d_out, int out_size)
{
    (void)in_sizes; (void)n_in; (void)out_size;
    const int*   prem  = (const int*)  d_in[0];
    const int*   hypo  = (const int*)  d_in[1];
    const float* embW  = (const float*)d_in[2];
    const float* distW = (const float*)d_in[3];
    const float* Ws1 = (const float*)d_in[4];  const float* bs1 = (const float*)d_in[5];
    const float* Ws2 = (const float*)d_in[6];  const float* bs2 = (const float*)d_in[7];
    const float* Wa1 = (const float*)d_in[8];  const float* ba1 = (const float*)d_in[9];
    const float* Wa2 = (const float*)d_in[10]; const float* ba2 = (const float*)d_in[11];
    const float* Wc1 = (const float*)d_in[12]; const float* bc1 = (const float*)d_in[13];
    const float* Wc2 = (const float*)d_in[14]; const float* bc2 = (const float*)d_in[15];
    const float* Wg1 = (const float*)d_in[16]; const float* bg1 = (const float*)d_in[17];
    const float* Wg2 = (const float*)d_in[18]; const float* bg2 = (const float*)d_in[19];
    const float* Wo  = (const float*)d_in[20];
    float* out = (float*)d_out;

    float *cmp_p, *cmp_h, *hid, *pq, *hk, *s1, *s2, *agg;
    int *mp, *mh;
    cudaGetSymbolAddress((void**)&cmp_p, g_cmp_p);
    cudaGetSymbolAddress((void**)&cmp_h, g_cmp_h);
    cudaGetSymbolAddress((void**)&hid,   g_hid);
    cudaGetSymbolAddress((void**)&pq,    g_pq);
    cudaGetSymbolAddress((void**)&hk,    g_hk);
    cudaGetSymbolAddress((void**)&s1,    g_s1);
    cudaGetSymbolAddress((void**)&s2,    g_s2);
    cudaGetSymbolAddress((void**)&agg,   g_agg);
    cudaGetSymbolAddress((void**)&mp,    g_mask_p);
    cudaGetSymbolAddress((void**)&mh,    g_mask_h);

    const long long SQ  = (long long)LL * DD;     // 256*512  per-batch Q stride
    const long long SS  = (long long)LL * LL;     // 256*256  per-batch score stride
    const long long SC  = (long long)LL * CATW;   // 256*2048 per-batch concat stride

    // embeddings -> concat[:, 0:512], masks
    embed_k<<<MROWS, 128>>>(prem, embW, cmp_p, mp);
    embed_k<<<MROWS, 128>>>(hypo, embW, cmp_h, mh);

    // ---- self branch: prem ----
    gemm(G_MLP, cmp_p, Ws1, bs1, hid, MROWS, DD, EE,   CATW, DD, DD, 0, 0, 0, 1);
    gemm(G_MLP, hid,   Ws2, bs2, pq,  MROWS, DD, DD,   DD,   DD, DD, 0, 0, 0, 1);
    gemm(G_NT,  pq, pq, nullptr, s1,  LL, LL, DD, DD, DD, LL, SQ, SQ, SS, BB);
    softmax_self_k<<<dim3(LL, BB), 256>>>(s1, mp, distW);
    gemm(G_NN,  s1, cmp_p, nullptr, cmp_p + EE, LL, EE, LL, LL, CATW, CATW, SS, SC, SC, BB);

    // ---- self branch: hypo ----
    gemm(G_MLP, cmp_h, Ws1, bs1, hid, MROWS, DD, EE,   CATW, DD, DD, 0, 0, 0, 1);
    gemm(G_MLP, hid,   Ws2, bs2, pq,  MROWS, DD, DD,   DD,   DD, DD, 0, 0, 0, 1);
    gemm(G_NT,  pq, pq, nullptr, s1,  LL, LL, DD, DD, DD, LL, SQ, SQ, SS, BB);
    softmax_self_k<<<dim3(LL, BB), 256>>>(s1, mh, distW);
    gemm(G_NN,  s1, cmp_h, nullptr, cmp_h + EE, LL, EE, LL, LL, CATW, CATW, SS, SC, SC, BB);

    // ---- inter attention ----
    gemm(G_MLP, cmp_p, Wa1, ba1, hid, MROWS, DD, 2 * EE, CATW, DD, DD, 0, 0, 0, 1);
    gemm(G_MLP, hid,   Wa2, ba2, pq,  MROWS, DD, DD,     DD,   DD, DD, 0, 0, 0, 1);
    gemm(G_MLP, cmp_h, Wa1, ba1, hid, MROWS, DD, 2 * EE, CATW, DD, DD, 0, 0, 0, 1);
    gemm(G_MLP, hid,   Wa2, ba2, hk,  MROWS, DD, DD,     DD,   DD, DD, 0, 0, 0, 1);
    gemm(G_NT,  pq, hk, nullptr, s1,  LL, LL, DD, DD, DD, LL, SQ, SQ, SS, BB);
    softmax_cols_k<<<dim3(LL, BB), 256>>>(s1, mp, s2);   // hypo2prem (reads cols of z)
    softmax_rows_k<<<dim3(LL, BB), 256>>>(s1, mh);       // prem2hypo (in place)
    // attended_hypo -> cmp_p[:, 1024:2048]
    gemm(G_NN, s1, cmp_h, nullptr, cmp_p + 2 * EE, LL, 2 * EE, LL, LL, CATW, CATW, SS, SC, SC, BB);
    // attended_prem -> cmp_h[:, 1024:2048]
    gemm(G_NN, s2, cmp_p, nullptr, cmp_h + 2 * EE, LL, 2 * EE, LL, LL, CATW, CATW, SS, SC, SC, BB);

    // ---- compare + masked sum ----
    gemm(G_MLP, cmp_p, Wc1, bc1, hid, MROWS, DD, 4 * EE, CATW, DD, DD, 0, 0, 0, 1);
    gemm(G_MLP, hid,   Wc2, bc2, pq,  MROWS, DD, DD,     DD,   DD, DD, 0, 0, 0, 1);
    masked_sum_k<<<dim3(DD / 128, BB), 128>>>(pq, mp, agg, 0);
    gemm(G_MLP, cmp_h, Wc1, bc1, hid, MROWS, DD, 4 * EE, CATW, DD, DD, 0, 0, 0, 1);
    gemm(G_MLP, hid,   Wc2, bc2, pq,  MROWS, DD, DD,     DD,   DD, DD, 0, 0, 0, 1);
    masked_sum_k<<<dim3(DD / 128, BB), 128>>>(pq, mh, agg, DD);

    // ---- aggregate MLP + output ----
    head_k<<<BB, DD>>>(agg, Wg1, bg1, Wg2, bg2, Wo, out);
}